// round 1
// baseline (speedup 1.0000x reference)
#include <cuda_runtime.h>
#include <mma.h>
#include <math.h>

using namespace nvcuda;

// Problem shapes (fixed by setup_inputs)
#define BATCH 65536
#define DIN   64
#define HID   512

// GEMM tile config
#define BM 128
#define BN 128
#define BKC 32
#define LDA 40    // 32 + 8 pad, multiple of 8
#define LDB 136   // 128 + 8 pad, multiple of 8
#define NTHREADS 256

// ---------------- scratch (device globals; no allocation) ----------------
__device__ __align__(256) float g_xm1[BATCH * DIN];
__device__ __align__(256) float g_s1[BATCH * HID];
__device__ __align__(256) float g_s2[BATCH * HID];
__device__ __align__(256) float g_s3[BATCH * HID];
__device__ __align__(256) float g_a1[BATCH * HID];
__device__ __align__(256) float g_a2[BATCH * HID];
__device__ __align__(256) float g_a3[BATCH * HID];
__device__ __align__(256) float g_d1[BATCH * HID];
__device__ __align__(256) float g_d2[BATCH * HID];
__device__ __align__(256) float g_d3[BATCH * HID];
__device__ __align__(256) float g_d4[BATCH * HID];

// ---------------- helpers ----------------
__global__ void sub1_kernel(const float* __restrict__ in, float* __restrict__ out, int n) {
    int i = blockIdx.x * blockDim.x + threadIdx.x;
    if (i < n) out[i] = in[i] - 1.0f;
}

__device__ __forceinline__ float softplusf(float p) {
    return (p > 20.0f) ? p : log1pf(expf(p));
}
__device__ __forceinline__ float sigmoidf_(float p) {
    return 1.0f / (1.0f + expf(-p));
}

// Epilogue modes
#define MODE_FWD 0   // out1 = sigmoid(p+b), out2 = softplus(p+b)
#define MODE_L4  1   // out1 = sigmoid(p+b) * vecn[col]
#define MODE_BWD 2   // out1 = sgate[row,col] * p
#define MODE_FIN 3   // out1 = p + vecn[col]

// Generic fused GEMM:
//   acc[i,j] = sum over up to 4 segments of  A_s[i,:] . W_s(:, j)
// BT=true : W_s is [N, K_s] row-major, used as W^T (forward layers)
// BT=false: W_s is [K_s, N] row-major (backward / final)
template<bool BT>
__global__ void __launch_bounds__(NTHREADS)
gemm_fused(const float* __restrict__ A0, const float* __restrict__ W0, int K0,
           const float* __restrict__ A1, const float* __restrict__ W1, int K1,
           const float* __restrict__ A2, const float* __restrict__ W2, int K2,
           const float* __restrict__ A3, const float* __restrict__ W3, int K3,
           int N,
           const float* __restrict__ bias,
           const float* __restrict__ vecn,
           const float* __restrict__ sgate,
           float* __restrict__ out1,
           float* __restrict__ out2,
           int mode)
{
    __shared__ float As[BM * LDA];
    __shared__ float Bs[BKC * LDB];

    const int tid    = threadIdx.x;
    const int warpId = tid >> 5;
    const int lane   = tid & 31;
    const int wm     = warpId >> 2;   // 0..1  (64-row slab)
    const int wn     = warpId & 3;    // 0..3  (32-col slab)
    const int m0     = blockIdx.y * BM;
    const int n0     = blockIdx.x * BN;

    wmma::fragment<wmma::accumulator, 16, 16, 8, float> acc[4][2];
    #pragma unroll
    for (int i = 0; i < 4; i++)
        #pragma unroll
        for (int j = 0; j < 2; j++)
            wmma::fill_fragment(acc[i][j], 0.0f);

    const float* Aseg[4] = {A0, A1, A2, A3};
    const float* Wseg[4] = {W0, W1, W2, W3};
    const int    Kseg[4] = {K0, K1, K2, K3};

    for (int s = 0; s < 4; s++) {
        const float* A = Aseg[s];
        const float* W = Wseg[s];
        const int K = Kseg[s];
        if (K == 0) continue;

        for (int k0 = 0; k0 < K; k0 += BKC) {
            __syncthreads();
            // ---- stage A tile [BM x BKC], tf32-converted ----
            #pragma unroll
            for (int t = 0; t < 4; t++) {
                int slot = tid + t * NTHREADS;      // 0..1023
                int row  = slot >> 3;               // /8
                int kq   = slot & 7;
                const float4 v = *reinterpret_cast<const float4*>(
                    A + (size_t)(m0 + row) * K + k0 + (kq << 2));
                float* dst = &As[row * LDA + (kq << 2)];
                dst[0] = wmma::__float_to_tf32(v.x);
                dst[1] = wmma::__float_to_tf32(v.y);
                dst[2] = wmma::__float_to_tf32(v.z);
                dst[3] = wmma::__float_to_tf32(v.w);
            }
            // ---- stage B tile [BKC x BN] into Bs[k][n] ----
            if (BT) {
                // W is [N, K] row-major; element (k,n) at W[(n0+n)*K + k]
                #pragma unroll
                for (int t = 0; t < 4; t++) {
                    int slot = tid + t * NTHREADS;
                    int n    = slot >> 3;
                    int kq   = slot & 7;
                    const float4 v = *reinterpret_cast<const float4*>(
                        W + (size_t)(n0 + n) * K + k0 + (kq << 2));
                    Bs[((kq << 2) + 0) * LDB + n] = wmma::__float_to_tf32(v.x);
                    Bs[((kq << 2) + 1) * LDB + n] = wmma::__float_to_tf32(v.y);
                    Bs[((kq << 2) + 2) * LDB + n] = wmma::__float_to_tf32(v.z);
                    Bs[((kq << 2) + 3) * LDB + n] = wmma::__float_to_tf32(v.w);
                }
            } else {
                // W is [K, N] row-major; element (k,n) at W[(k0+k)*N + n]
                #pragma unroll
                for (int t = 0; t < 4; t++) {
                    int slot = tid + t * NTHREADS;
                    int krow = slot >> 5;
                    int nq   = slot & 31;
                    int nn   = n0 + (nq << 2);
                    float4 v = make_float4(0.f, 0.f, 0.f, 0.f);
                    if (nn < N)
                        v = *reinterpret_cast<const float4*>(
                            W + (size_t)(k0 + krow) * N + nn);
                    float* dst = &Bs[krow * LDB + (nq << 2)];
                    dst[0] = wmma::__float_to_tf32(v.x);
                    dst[1] = wmma::__float_to_tf32(v.y);
                    dst[2] = wmma::__float_to_tf32(v.z);
                    dst[3] = wmma::__float_to_tf32(v.w);
                }
            }
            __syncthreads();

            // ---- compute: 4 k-steps of m16n16k8 tf32 ----
            #pragma unroll
            for (int kk = 0; kk < BKC; kk += 8) {
                wmma::fragment<wmma::matrix_a, 16, 16, 8, wmma::precision::tf32, wmma::row_major> af[4];
                wmma::fragment<wmma::matrix_b, 16, 16, 8, wmma::precision::tf32, wmma::row_major> bf[2];
                #pragma unroll
                for (int i = 0; i < 4; i++)
                    wmma::load_matrix_sync(af[i], &As[(wm * 64 + i * 16) * LDA + kk], LDA);
                #pragma unroll
                for (int j = 0; j < 2; j++)
                    wmma::load_matrix_sync(bf[j], &Bs[kk * LDB + wn * 32 + j * 16], LDB);
                #pragma unroll
                for (int i = 0; i < 4; i++)
                    #pragma unroll
                    for (int j = 0; j < 2; j++)
                        wmma::mma_sync(acc[i][j], af[i], bf[j], acc[i][j]);
            }
        }
    }

    // ---- epilogue: per-warp smem staging, elementwise, write out ----
    __syncthreads();
    float* ep = &As[warpId * 288];  // 256 used, 288 spacing keeps 16B alignment

    #pragma unroll
    for (int i = 0; i < 4; i++) {
        #pragma unroll
        for (int j = 0; j < 2; j++) {
            const int rbase = m0 + wm * 64 + i * 16;
            const int cbase = n0 + wn * 32 + j * 16;
            wmma::store_matrix_sync(ep, acc[i][j], 16, wmma::mem_row_major);
            __syncwarp();
            #pragma unroll
            for (int e = 0; e < 8; e++) {
                int lin = e * 32 + lane;       // coalesced: half-warp per 16-wide row
                int r = lin >> 4;
                int c = lin & 15;
                int col = cbase + c;
                if (col < N) {
                    float p = ep[lin];
                    size_t oi = (size_t)(rbase + r) * N + col;
                    if (mode == MODE_FWD) {
                        p += bias[col];
                        out1[oi] = sigmoidf_(p);
                        out2[oi] = softplusf(p);
                    } else if (mode == MODE_L4) {
                        p += bias[col];
                        out1[oi] = vecn[col] * sigmoidf_(p);
                    } else if (mode == MODE_BWD) {
                        out1[oi] = sgate[oi] * p;
                    } else { // MODE_FIN
                        out1[oi] = p + vecn[col];
                    }
                }
            }
            __syncwarp();
        }
    }
}

// ---------------- host launcher ----------------
extern "C" void kernel_launch(void* const* d_in, const int* in_sizes, int n_in,
                              void* d_out, int out_size)
{
    const float* state = (const float*)d_in[0];
    const float* Wz0   = (const float*)d_in[1];
    const float* bz0   = (const float*)d_in[2];
    const float* Wz1   = (const float*)d_in[3];
    const float* Wz2   = (const float*)d_in[4];
    const float* Wz3   = (const float*)d_in[5];
    const float* WzL   = (const float*)d_in[6];
    const float* Wx0   = (const float*)d_in[7];
    const float* bx0   = (const float*)d_in[8];
    const float* Wx1   = (const float*)d_in[9];
    const float* bx1   = (const float*)d_in[10];
    const float* Wx2   = (const float*)d_in[11];
    const float* bx2   = (const float*)d_in[12];
    const float* WxL   = (const float*)d_in[13];
    float* out = (float*)d_out;

    void* p;
    float *xm1, *s1, *s2, *s3, *a1, *a2, *a3, *d1, *d2, *d3, *d4;
    cudaGetSymbolAddress(&p, g_xm1); xm1 = (float*)p;
    cudaGetSymbolAddress(&p, g_s1);  s1  = (float*)p;
    cudaGetSymbolAddress(&p, g_s2);  s2  = (float*)p;
    cudaGetSymbolAddress(&p, g_s3);  s3  = (float*)p;
    cudaGetSymbolAddress(&p, g_a1);  a1  = (float*)p;
    cudaGetSymbolAddress(&p, g_a2);  a2  = (float*)p;
    cudaGetSymbolAddress(&p, g_a3);  a3  = (float*)p;
    cudaGetSymbolAddress(&p, g_d1);  d1  = (float*)p;
    cudaGetSymbolAddress(&p, g_d2);  d2  = (float*)p;
    cudaGetSymbolAddress(&p, g_d3);  d3  = (float*)p;
    cudaGetSymbolAddress(&p, g_d4);  d4  = (float*)p;

    const int nX = BATCH * DIN;
    sub1_kernel<<<(nX + 255) / 256, 256>>>(state, xm1, nX);

    dim3 blk(NTHREADS);
    dim3 gH(HID / BN, BATCH / BM);   // (4, 512)
    dim3 gF(1, BATCH / BM);          // (1, 512), N=64 < BN

    // Forward
    // L1: p1 = xm1 @ Wz0^T + bz0  -> s1, a1
    gemm_fused<true><<<gH, blk>>>(xm1, Wz0, DIN,
                                  nullptr, nullptr, 0,
                                  nullptr, nullptr, 0,
                                  nullptr, nullptr, 0,
                                  HID, bz0, nullptr, nullptr, s1, a1, MODE_FWD);
    // L2: p2 = a1 @ Wz1^T + xm1 @ Wx0^T + bx0 -> s2, a2
    gemm_fused<true><<<gH, blk>>>(a1, Wz1, HID,
                                  xm1, Wx0, DIN,
                                  nullptr, nullptr, 0,
                                  nullptr, nullptr, 0,
                                  HID, bx0, nullptr, nullptr, s2, a2, MODE_FWD);
    // L3
    gemm_fused<true><<<gH, blk>>>(a2, Wz2, HID,
                                  xm1, Wx1, DIN,
                                  nullptr, nullptr, 0,
                                  nullptr, nullptr, 0,
                                  HID, bx1, nullptr, nullptr, s3, a3, MODE_FWD);
    // L4: p4 = a3 @ Wz3^T + xm1 @ Wx2^T + bx2 -> d4 = WzL * sigmoid(p4)
    gemm_fused<true><<<gH, blk>>>(a3, Wz3, HID,
                                  xm1, Wx2, DIN,
                                  nullptr, nullptr, 0,
                                  nullptr, nullptr, 0,
                                  HID, bx2, WzL, nullptr, d4, nullptr, MODE_L4);

    // Backward (u = d_next @ Wz_k row-major; d = s ⊙ u)
    gemm_fused<false><<<gH, blk>>>(d4, Wz3, HID,
                                   nullptr, nullptr, 0,
                                   nullptr, nullptr, 0,
                                   nullptr, nullptr, 0,
                                   HID, nullptr, nullptr, s3, d3, nullptr, MODE_BWD);
    gemm_fused<false><<<gH, blk>>>(d3, Wz2, HID,
                                   nullptr, nullptr, 0,
                                   nullptr, nullptr, 0,
                                   nullptr, nullptr, 0,
                                   HID, nullptr, nullptr, s2, d2, nullptr, MODE_BWD);
    gemm_fused<false><<<gH, blk>>>(d2, Wz1, HID,
                                   nullptr, nullptr, 0,
                                   nullptr, nullptr, 0,
                                   nullptr, nullptr, 0,
                                   HID, nullptr, nullptr, s1, d1, nullptr, MODE_BWD);

    // Final: action = WxL + d1@Wz0 + d2@Wx0 + d3@Wx1 + d4@Wx2
    gemm_fused<false><<<gF, blk>>>(d1, Wz0, HID,
                                   d2, Wx0, HID,
                                   d3, Wx1, HID,
                                   d4, Wx2, HID,
                                   DIN, nullptr, WxL, nullptr, out, nullptr, MODE_FIN);
}

// round 6
// speedup vs baseline: 1.8596x; 1.8596x over previous
#include <cuda_runtime.h>
#include <mma.h>
#include <math.h>
#include <cstdint>

using namespace nvcuda;

// Problem shapes (fixed by setup_inputs)
#define BATCH 65536
#define DIN   64
#define HID   512

// GEMM tile config
#define BM 128
#define BN 128
#define BKC 32
#define LDA 40    // 32 + 8 pad (floats), row stride 160B (16B-aligned)
#define LDB 136   // 128 + 8 pad (floats), row stride 544B (16B-aligned)
#define NTHREADS 256

#define A_STAGE_FLOATS (BM * LDA)          // 5120
#define W_STAGE_FLOATS (BM * LDA)          // 5120 (max of BT-true 128x40 and BT-false 32x136=4352)
#define STAGE_FLOATS   (A_STAGE_FLOATS + W_STAGE_FLOATS)   // 10240
#define SMEM_BYTES     (2 * STAGE_FLOATS * 4)              // 81920

// ---------------- scratch (device globals; no allocation) ----------------
__device__ __align__(256) float g_xm1[BATCH * DIN];
__device__ __align__(256) float g_s1[BATCH * HID];
__device__ __align__(256) float g_s2[BATCH * HID];
__device__ __align__(256) float g_s3[BATCH * HID];
__device__ __align__(256) float g_a1[BATCH * HID];
__device__ __align__(256) float g_a2[BATCH * HID];
__device__ __align__(256) float g_a3[BATCH * HID];
__device__ __align__(256) float g_d1[BATCH * HID];
__device__ __align__(256) float g_d2[BATCH * HID];
__device__ __align__(256) float g_d3[BATCH * HID];
__device__ __align__(256) float g_d4[BATCH * HID];

// ---------------- helpers ----------------
__global__ void sub1_kernel(const float* __restrict__ in, float* __restrict__ out, int n) {
    int i = blockIdx.x * blockDim.x + threadIdx.x;
    if (i < n) out[i] = in[i] - 1.0f;
}

__device__ __forceinline__ float softplusf(float p) {
    return (p > 20.0f) ? p : log1pf(expf(p));
}
__device__ __forceinline__ float sigmoidf_(float p) {
    return 1.0f / (1.0f + expf(-p));
}

__device__ __forceinline__ void cp_async16(float* smem_dst, const float* gmem_src, bool pred) {
    unsigned int s = (unsigned int)__cvta_generic_to_shared(smem_dst);
    int bytes = pred ? 16 : 0;
    asm volatile("cp.async.cg.shared.global [%0], [%1], 16, %2;\n"
                 :: "r"(s), "l"(gmem_src), "r"(bytes));
}
__device__ __forceinline__ void cp_async_commit() {
    asm volatile("cp.async.commit_group;\n" ::: "memory");
}
__device__ __forceinline__ void cp_async_wait1() {
    asm volatile("cp.async.wait_group 1;\n" ::: "memory");
}

// Epilogue modes
#define MODE_FWD 0   // out1 = sigmoid(p+b), out2 = softplus(p+b)
#define MODE_L4  1   // out1 = sigmoid(p+b) * vecn[col]
#define MODE_BWD 2   // out1 = sgate[row,col] * p
#define MODE_FIN 3   // out1 = p + vecn[col]

// Map flattened k-iteration index -> (A, W, K, k0) across up to 4 segments.
__device__ __forceinline__ void get_iter(
    int it,
    const float* A0, const float* W0, int K0,
    const float* A1, const float* W1, int K1,
    const float* A2, const float* W2, int K2,
    const float* A3, const float* W3, int K3,
    const float*& A, const float*& W, int& K, int& k0)
{
    int n0 = K0 >> 5;
    if (it < n0) { A = A0; W = W0; K = K0; k0 = it << 5; return; }
    it -= n0;
    int n1 = K1 >> 5;
    if (it < n1) { A = A1; W = W1; K = K1; k0 = it << 5; return; }
    it -= n1;
    int n2 = K2 >> 5;
    if (it < n2) { A = A2; W = W2; K = K2; k0 = it << 5; return; }
    it -= n2;
    A = A3; W = W3; K = K3; k0 = it << 5;
}

// Stage one (A tile, W tile) pair into stage buffers via cp.async.
// BT=true : W is [N,K] row-major, staged untransposed as sW[n][k] (col_major b-frag).
// BT=false: W is [K,N] row-major, staged as sW[k][n] (row_major b-frag).
template<bool BT>
__device__ __forceinline__ void stage_tiles(
    float* sA, float* sW,
    const float* __restrict__ A, const float* __restrict__ W,
    int K, int k0, int m0, int n0, int N, int tid)
{
    // A tile: 128 rows x 32 k-floats = 1024 16B chunks, 4 per thread
    #pragma unroll
    for (int t = 0; t < 4; t++) {
        int slot = tid + t * NTHREADS;
        int row  = slot >> 3;
        int kq   = slot & 7;
        cp_async16(&sA[row * LDA + (kq << 2)],
                   A + (size_t)(m0 + row) * K + k0 + (kq << 2), true);
    }
    if (BT) {
        // W[N,K]: rows n0..n0+127, k-chunk k0..k0+31 -> sW[n*LDA + k]
        #pragma unroll
        for (int t = 0; t < 4; t++) {
            int slot = tid + t * NTHREADS;
            int n    = slot >> 3;
            int kq   = slot & 7;
            cp_async16(&sW[n * LDA + (kq << 2)],
                       W + (size_t)(n0 + n) * K + k0 + (kq << 2), true);
        }
    } else {
        // W[K,N]: rows k0..k0+31, cols n0..n0+127 -> sW[k*LDB + n]
        // 32 rows x 32 chunks = 1024 chunks, 4 per thread
        #pragma unroll
        for (int t = 0; t < 4; t++) {
            int slot = tid + t * NTHREADS;
            int krow = slot >> 5;          // 0..31
            int nq   = slot & 31;          // 0..31
            int col  = n0 + (nq << 2);
            cp_async16(&sW[krow * LDB + (nq << 2)],
                       W + (size_t)(k0 + krow) * N + col, col < N);
        }
    }
}

template<typename Frag>
__device__ __forceinline__ void round_frag_tf32(Frag& f) {
    #pragma unroll
    for (int t = 0; t < f.num_elements; t++)
        f.x[t] = wmma::__float_to_tf32(f.x[t]);
}

// Generic fused GEMM with 2-stage cp.async pipeline.
template<bool BT>
__global__ void __launch_bounds__(NTHREADS, 2)
gemm_fused(const float* __restrict__ A0, const float* __restrict__ W0, int K0,
           const float* __restrict__ A1, const float* __restrict__ W1, int K1,
           const float* __restrict__ A2, const float* __restrict__ W2, int K2,
           const float* __restrict__ A3, const float* __restrict__ W3, int K3,
           int N,
           const float* __restrict__ bias,
           const float* __restrict__ vecn,
           const float* __restrict__ sgate,
           float* __restrict__ out1,
           float* __restrict__ out2,
           int mode)
{
    extern __shared__ float smem[];

    const int tid    = threadIdx.x;
    const int warpId = tid >> 5;
    const int lane   = tid & 31;
    const int wm     = warpId >> 2;   // 0..1  (64-row slab)
    const int wn     = warpId & 3;    // 0..3  (32-col slab)
    const int m0     = blockIdx.y * BM;
    const int n0     = blockIdx.x * BN;

    wmma::fragment<wmma::accumulator, 16, 16, 8, float> acc[4][2];
    #pragma unroll
    for (int i = 0; i < 4; i++)
        #pragma unroll
        for (int j = 0; j < 2; j++)
            wmma::fill_fragment(acc[i][j], 0.0f);

    const int total_iters = (K0 >> 5) + (K1 >> 5) + (K2 >> 5) + (K3 >> 5);

    // Prologue: stage iter 0 into buffer 0
    {
        const float *A, *W; int K, k0;
        get_iter(0, A0,W0,K0, A1,W1,K1, A2,W2,K2, A3,W3,K3, A, W, K, k0);
        stage_tiles<BT>(smem, smem + A_STAGE_FLOATS, A, W, K, k0, m0, n0, N, tid);
    }
    cp_async_commit();

    for (int it = 0; it < total_iters; ++it) {
        const int cur = it & 1;
        float* sA = smem + cur * STAGE_FLOATS;
        float* sW = sA + A_STAGE_FLOATS;

        // Prefetch next iteration into the other buffer
        if (it + 1 < total_iters) {
            const float *A, *W; int K, k0;
            get_iter(it + 1, A0,W0,K0, A1,W1,K1, A2,W2,K2, A3,W3,K3, A, W, K, k0);
            float* nA = smem + (cur ^ 1) * STAGE_FLOATS;
            stage_tiles<BT>(nA, nA + A_STAGE_FLOATS, A, W, K, k0, m0, n0, N, tid);
        }
        cp_async_commit();
        cp_async_wait1();     // current stage's group complete
        __syncthreads();

        // ---- compute: 4 k-steps of m16n16k8 tf32 ----
        #pragma unroll
        for (int kk = 0; kk < BKC; kk += 8) {
            wmma::fragment<wmma::matrix_a, 16, 16, 8, wmma::precision::tf32, wmma::row_major> af[4];
            #pragma unroll
            for (int i = 0; i < 4; i++) {
                wmma::load_matrix_sync(af[i], &sA[(wm * 64 + i * 16) * LDA + kk], LDA);
                round_frag_tf32(af[i]);
            }
            if (BT) {
                wmma::fragment<wmma::matrix_b, 16, 16, 8, wmma::precision::tf32, wmma::col_major> bf[2];
                #pragma unroll
                for (int j = 0; j < 2; j++) {
                    wmma::load_matrix_sync(bf[j], &sW[(wn * 32 + j * 16) * LDA + kk], LDA);
                    round_frag_tf32(bf[j]);
                }
                #pragma unroll
                for (int i = 0; i < 4; i++)
                    #pragma unroll
                    for (int j = 0; j < 2; j++)
                        wmma::mma_sync(acc[i][j], af[i], bf[j], acc[i][j]);
            } else {
                wmma::fragment<wmma::matrix_b, 16, 16, 8, wmma::precision::tf32, wmma::row_major> bf[2];
                #pragma unroll
                for (int j = 0; j < 2; j++) {
                    wmma::load_matrix_sync(bf[j], &sW[kk * LDB + wn * 32 + j * 16], LDB);
                    round_frag_tf32(bf[j]);
                }
                #pragma unroll
                for (int i = 0; i < 4; i++)
                    #pragma unroll
                    for (int j = 0; j < 2; j++)
                        wmma::mma_sync(acc[i][j], af[i], bf[j], acc[i][j]);
            }
        }
        __syncthreads();   // protect 'cur' buffer before it is re-staged next iteration
    }

    // ---- epilogue: per-warp smem staging, elementwise, write out ----
    float* ep = &smem[warpId * 288];  // 256 used, 288 spacing keeps 16B alignment

    #pragma unroll
    for (int i = 0; i < 4; i++) {
        #pragma unroll
        for (int j = 0; j < 2; j++) {
            const int rbase = m0 + wm * 64 + i * 16;
            const int cbase = n0 + wn * 32 + j * 16;
            wmma::store_matrix_sync(ep, acc[i][j], 16, wmma::mem_row_major);
            __syncwarp();
            #pragma unroll
            for (int e = 0; e < 8; e++) {
                int lin = e * 32 + lane;       // coalesced: half-warp per 16-wide row
                int r = lin >> 4;
                int c = lin & 15;
                int col = cbase + c;
                if (col < N) {
                    float p = ep[lin];
                    size_t oi = (size_t)(rbase + r) * N + col;
                    if (mode == MODE_FWD) {
                        p += bias[col];
                        out1[oi] = sigmoidf_(p);
                        out2[oi] = softplusf(p);
                    } else if (mode == MODE_L4) {
                        p += bias[col];
                        out1[oi] = vecn[col] * sigmoidf_(p);
                    } else if (mode == MODE_BWD) {
                        out1[oi] = sgate[oi] * p;
                    } else { // MODE_FIN
                        out1[oi] = p + vecn[col];
                    }
                }
            }
            __syncwarp();
        }
    }
}

// ---------------- host launcher ----------------
extern "C" void kernel_launch(void* const* d_in, const int* in_sizes, int n_in,
                              void* d_out, int out_size)
{
    const float* state = (const float*)d_in[0];
    const float* Wz0   = (const float*)d_in[1];
    const float* bz0   = (const float*)d_in[2];
    const float* Wz1   = (const float*)d_in[3];
    const float* Wz2   = (const float*)d_in[4];
    const float* Wz3   = (const float*)d_in[5];
    const float* WzL   = (const float*)d_in[6];
    const float* Wx0   = (const float*)d_in[7];
    const float* bx0   = (const float*)d_in[8];
    const float* Wx1   = (const float*)d_in[9];
    const float* bx1   = (const float*)d_in[10];
    const float* Wx2   = (const float*)d_in[11];
    const float* bx2   = (const float*)d_in[12];
    const float* WxL   = (const float*)d_in[13];
    float* out = (float*)d_out;

    cudaFuncSetAttribute(gemm_fused<true>,  cudaFuncAttributeMaxDynamicSharedMemorySize, SMEM_BYTES);
    cudaFuncSetAttribute(gemm_fused<false>, cudaFuncAttributeMaxDynamicSharedMemorySize, SMEM_BYTES);

    void* p;
    float *xm1, *s1, *s2, *s3, *a1, *a2, *a3, *d1, *d2, *d3, *d4;
    cudaGetSymbolAddress(&p, g_xm1); xm1 = (float*)p;
    cudaGetSymbolAddress(&p, g_s1);  s1  = (float*)p;
    cudaGetSymbolAddress(&p, g_s2);  s2  = (float*)p;
    cudaGetSymbolAddress(&p, g_s3);  s3  = (float*)p;
    cudaGetSymbolAddress(&p, g_a1);  a1  = (float*)p;
    cudaGetSymbolAddress(&p, g_a2);  a2  = (float*)p;
    cudaGetSymbolAddress(&p, g_a3);  a3  = (float*)p;
    cudaGetSymbolAddress(&p, g_d1);  d1  = (float*)p;
    cudaGetSymbolAddress(&p, g_d2);  d2  = (float*)p;
    cudaGetSymbolAddress(&p, g_d3);  d3  = (float*)p;
    cudaGetSymbolAddress(&p, g_d4);  d4  = (float*)p;

    const int nX = BATCH * DIN;
    sub1_kernel<<<(nX + 255) / 256, 256>>>(state, xm1, nX);

    dim3 blk(NTHREADS);
    dim3 gH(HID / BN, BATCH / BM);   // (4, 512)
    dim3 gF(1, BATCH / BM);          // (1, 512), N=64 < BN

    // Forward
    gemm_fused<true><<<gH, blk, SMEM_BYTES>>>(xm1, Wz0, DIN,
                                  nullptr, nullptr, 0,
                                  nullptr, nullptr, 0,
                                  nullptr, nullptr, 0,
                                  HID, bz0, nullptr, nullptr, s1, a1, MODE_FWD);
    gemm_fused<true><<<gH, blk, SMEM_BYTES>>>(a1, Wz1, HID,
                                  xm1, Wx0, DIN,
                                  nullptr, nullptr, 0,
                                  nullptr, nullptr, 0,
                                  HID, bx0, nullptr, nullptr, s2, a2, MODE_FWD);
    gemm_fused<true><<<gH, blk, SMEM_BYTES>>>(a2, Wz2, HID,
                                  xm1, Wx1, DIN,
                                  nullptr, nullptr, 0,
                                  nullptr, nullptr, 0,
                                  HID, bx1, nullptr, nullptr, s3, a3, MODE_FWD);
    gemm_fused<true><<<gH, blk, SMEM_BYTES>>>(a3, Wz3, HID,
                                  xm1, Wx2, DIN,
                                  nullptr, nullptr, 0,
                                  nullptr, nullptr, 0,
                                  HID, bx2, WzL, nullptr, d4, nullptr, MODE_L4);

    // Backward (u = d_next @ Wz_k row-major; d = s ⊙ u)
    gemm_fused<false><<<gH, blk, SMEM_BYTES>>>(d4, Wz3, HID,
                                   nullptr, nullptr, 0,
                                   nullptr, nullptr, 0,
                                   nullptr, nullptr, 0,
                                   HID, nullptr, nullptr, s3, d3, nullptr, MODE_BWD);
    gemm_fused<false><<<gH, blk, SMEM_BYTES>>>(d3, Wz2, HID,
                                   nullptr, nullptr, 0,
                                   nullptr, nullptr, 0,
                                   nullptr, nullptr, 0,
                                   HID, nullptr, nullptr, s2, d2, nullptr, MODE_BWD);
    gemm_fused<false><<<gH, blk, SMEM_BYTES>>>(d2, Wz1, HID,
                                   nullptr, nullptr, 0,
                                   nullptr, nullptr, 0,
                                   nullptr, nullptr, 0,
                                   HID, nullptr, nullptr, s1, d1, nullptr, MODE_BWD);

    // Final: action = WxL + d1@Wz0 + d2@Wx0 + d3@Wx1 + d4@Wx2
    gemm_fused<false><<<gF, blk, SMEM_BYTES>>>(d1, Wz0, HID,
                                   d2, Wx0, HID,
                                   d3, Wx1, HID,
                                   d4, Wx2, HID,
                                   DIN, nullptr, WxL, nullptr, out, nullptr, MODE_FIN);
}

// round 7
// speedup vs baseline: 1.9836x; 1.0667x over previous
#include <cuda_runtime.h>
#include <mma.h>
#include <math.h>
#include <cstdint>

using namespace nvcuda;

// Problem shapes (fixed by setup_inputs)
#define BATCH 65536
#define DIN   64
#define HID   512

// GEMM tile config
#define BM 128
#define BN 128
#define BKC 32
#define LDA 40    // 32 + 8 pad (floats)
#define LDB 136   // 128 + 8 pad (floats)
#define NTHREADS 256

#define A_STAGE_FLOATS (BM * LDA)          // 5120
#define W_STAGE_FLOATS (BM * LDA)          // 5120
#define STAGE_FLOATS   (A_STAGE_FLOATS + W_STAGE_FLOATS)   // 10240
#define SMEM_BYTES     (2 * STAGE_FLOATS * 4)              // 81920

// ---------------- scratch (device globals; no allocation) ----------------
__device__ __align__(256) float g_xm1[BATCH * DIN];
__device__ __align__(256) float g_s1[BATCH * HID];
__device__ __align__(256) float g_s2[BATCH * HID];
__device__ __align__(256) float g_s3[BATCH * HID];
__device__ __align__(256) float g_a1[BATCH * HID];
__device__ __align__(256) float g_a2[BATCH * HID];
__device__ __align__(256) float g_a3[BATCH * HID];
__device__ __align__(256) float g_d1[BATCH * HID];
__device__ __align__(256) float g_d2[BATCH * HID];
__device__ __align__(256) float g_d3[BATCH * HID];
__device__ __align__(256) float g_d4[BATCH * HID];
// tf32-rounded weight copies
__device__ __align__(256) float g_wz0[HID * DIN];
__device__ __align__(256) float g_wz1[HID * HID];
__device__ __align__(256) float g_wz2[HID * HID];
__device__ __align__(256) float g_wz3[HID * HID];
__device__ __align__(256) float g_wx0[HID * DIN];
__device__ __align__(256) float g_wx1[HID * DIN];
__device__ __align__(256) float g_wx2[HID * DIN];

// ---------------- helpers ----------------
__global__ void sub1_kernel(const float* __restrict__ in, float* __restrict__ out, int n) {
    int i = blockIdx.x * blockDim.x + threadIdx.x;
    if (i < n) out[i] = wmma::__float_to_tf32(in[i] - 1.0f);
}

__global__ void round_copy_kernel(const float* __restrict__ in, float* __restrict__ out, int n) {
    int i = blockIdx.x * blockDim.x + threadIdx.x;
    if (i < n) out[i] = wmma::__float_to_tf32(in[i]);
}

__device__ __forceinline__ float softplusf(float p) {
    return (p > 20.0f) ? p : log1pf(expf(p));
}
__device__ __forceinline__ float sigmoidf_(float p) {
    return 1.0f / (1.0f + expf(-p));
}

__device__ __forceinline__ void cp_async16(float* smem_dst, const float* gmem_src, bool pred) {
    unsigned int s = (unsigned int)__cvta_generic_to_shared(smem_dst);
    int bytes = pred ? 16 : 0;
    asm volatile("cp.async.cg.shared.global [%0], [%1], 16, %2;\n"
                 :: "r"(s), "l"(gmem_src), "r"(bytes));
}
__device__ __forceinline__ void cp_async_commit() {
    asm volatile("cp.async.commit_group;\n" ::: "memory");
}
__device__ __forceinline__ void cp_async_wait1() {
    asm volatile("cp.async.wait_group 1;\n" ::: "memory");
}

// Epilogue modes
#define MODE_FWD 0   // out1 = sigmoid(p+b), out2 = tf32(softplus(p+b))
#define MODE_L4  1   // out1 = tf32(sigmoid(p+b) * vecn[col])
#define MODE_BWD 2   // out1 = tf32(sgate[row,col] * p)
#define MODE_FIN 3   // out1 = p + vecn[col]

// Map flattened k-iteration index -> (A, W, K, k0) across up to 4 segments.
__device__ __forceinline__ void get_iter(
    int it,
    const float* A0, const float* W0, int K0,
    const float* A1, const float* W1, int K1,
    const float* A2, const float* W2, int K2,
    const float* A3, const float* W3, int K3,
    const float*& A, const float*& W, int& K, int& k0)
{
    int n0 = K0 >> 5;
    if (it < n0) { A = A0; W = W0; K = K0; k0 = it << 5; return; }
    it -= n0;
    int n1 = K1 >> 5;
    if (it < n1) { A = A1; W = W1; K = K1; k0 = it << 5; return; }
    it -= n1;
    int n2 = K2 >> 5;
    if (it < n2) { A = A2; W = W2; K = K2; k0 = it << 5; return; }
    it -= n2;
    A = A3; W = W3; K = K3; k0 = it << 5;
}

// Stage one (A tile, W tile) pair into stage buffers via cp.async.
template<bool BT>
__device__ __forceinline__ void stage_tiles(
    float* sA, float* sW,
    const float* __restrict__ A, const float* __restrict__ W,
    int K, int k0, int m0, int n0, int N, int tid)
{
    #pragma unroll
    for (int t = 0; t < 4; t++) {
        int slot = tid + t * NTHREADS;
        int row  = slot >> 3;
        int kq   = slot & 7;
        cp_async16(&sA[row * LDA + (kq << 2)],
                   A + (size_t)(m0 + row) * K + k0 + (kq << 2), true);
    }
    if (BT) {
        // W[N,K]: rows n0..n0+127 -> sW[n*LDA + k]
        #pragma unroll
        for (int t = 0; t < 4; t++) {
            int slot = tid + t * NTHREADS;
            int n    = slot >> 3;
            int kq   = slot & 7;
            cp_async16(&sW[n * LDA + (kq << 2)],
                       W + (size_t)(n0 + n) * K + k0 + (kq << 2), true);
        }
    } else {
        // W[K,N]: rows k0..k0+31, cols n0..n0+127 -> sW[k*LDB + n]
        #pragma unroll
        for (int t = 0; t < 4; t++) {
            int slot = tid + t * NTHREADS;
            int krow = slot >> 5;
            int nq   = slot & 31;
            int col  = n0 + (nq << 2);
            cp_async16(&sW[krow * LDB + (nq << 2)],
                       W + (size_t)(k0 + krow) * N + col, col < N);
        }
    }
}

// Generic fused GEMM with 2-stage cp.async pipeline.
// All GEMM inputs must already be tf32-rounded in gmem.
template<bool BT, int MODE>
__global__ void __launch_bounds__(NTHREADS, 2)
gemm_fused(const float* __restrict__ A0, const float* __restrict__ W0, int K0,
           const float* __restrict__ A1, const float* __restrict__ W1, int K1,
           const float* __restrict__ A2, const float* __restrict__ W2, int K2,
           const float* __restrict__ A3, const float* __restrict__ W3, int K3,
           int N,
           const float* __restrict__ bias,
           const float* __restrict__ vecn,
           const float* __restrict__ sgate,
           float* __restrict__ out1,
           float* __restrict__ out2)
{
    extern __shared__ float smem[];

    const int tid    = threadIdx.x;
    const int warpId = tid >> 5;
    const int lane   = tid & 31;
    const int wm     = warpId >> 2;
    const int wn     = warpId & 3;
    const int m0     = blockIdx.y * BM;
    const int n0     = blockIdx.x * BN;

    wmma::fragment<wmma::accumulator, 16, 16, 8, float> acc[4][2];
    #pragma unroll
    for (int i = 0; i < 4; i++)
        #pragma unroll
        for (int j = 0; j < 2; j++)
            wmma::fill_fragment(acc[i][j], 0.0f);

    const int total_iters = (K0 >> 5) + (K1 >> 5) + (K2 >> 5) + (K3 >> 5);

    {
        const float *A, *W; int K, k0;
        get_iter(0, A0,W0,K0, A1,W1,K1, A2,W2,K2, A3,W3,K3, A, W, K, k0);
        stage_tiles<BT>(smem, smem + A_STAGE_FLOATS, A, W, K, k0, m0, n0, N, tid);
    }
    cp_async_commit();

    for (int it = 0; it < total_iters; ++it) {
        const int cur = it & 1;
        float* sA = smem + cur * STAGE_FLOATS;
        float* sW = sA + A_STAGE_FLOATS;

        if (it + 1 < total_iters) {
            const float *A, *W; int K, k0;
            get_iter(it + 1, A0,W0,K0, A1,W1,K1, A2,W2,K2, A3,W3,K3, A, W, K, k0);
            float* nA = smem + (cur ^ 1) * STAGE_FLOATS;
            stage_tiles<BT>(nA, nA + A_STAGE_FLOATS, A, W, K, k0, m0, n0, N, tid);
        }
        cp_async_commit();
        cp_async_wait1();
        __syncthreads();

        #pragma unroll
        for (int kk = 0; kk < BKC; kk += 8) {
            wmma::fragment<wmma::matrix_a, 16, 16, 8, wmma::precision::tf32, wmma::row_major> af[4];
            #pragma unroll
            for (int i = 0; i < 4; i++)
                wmma::load_matrix_sync(af[i], &sA[(wm * 64 + i * 16) * LDA + kk], LDA);
            if (BT) {
                wmma::fragment<wmma::matrix_b, 16, 16, 8, wmma::precision::tf32, wmma::col_major> bf[2];
                #pragma unroll
                for (int j = 0; j < 2; j++)
                    wmma::load_matrix_sync(bf[j], &sW[(wn * 32 + j * 16) * LDA + kk], LDA);
                #pragma unroll
                for (int i = 0; i < 4; i++)
                    #pragma unroll
                    for (int j = 0; j < 2; j++)
                        wmma::mma_sync(acc[i][j], af[i], bf[j], acc[i][j]);
            } else {
                wmma::fragment<wmma::matrix_b, 16, 16, 8, wmma::precision::tf32, wmma::row_major> bf[2];
                #pragma unroll
                for (int j = 0; j < 2; j++)
                    wmma::load_matrix_sync(bf[j], &sW[kk * LDB + wn * 32 + j * 16], LDB);
                #pragma unroll
                for (int i = 0; i < 4; i++)
                    #pragma unroll
                    for (int j = 0; j < 2; j++)
                        wmma::mma_sync(acc[i][j], af[i], bf[j], acc[i][j]);
            }
        }
        __syncthreads();
    }

    // ---- epilogue ----
    float* ep = &smem[warpId * 288];

    #pragma unroll
    for (int i = 0; i < 4; i++) {
        #pragma unroll
        for (int j = 0; j < 2; j++) {
            const int rbase = m0 + wm * 64 + i * 16;
            const int cbase = n0 + wn * 32 + j * 16;
            wmma::store_matrix_sync(ep, acc[i][j], 16, wmma::mem_row_major);
            __syncwarp();
            #pragma unroll
            for (int e = 0; e < 8; e++) {
                int lin = e * 32 + lane;
                int r = lin >> 4;
                int c = lin & 15;
                int col = cbase + c;
                if (col < N) {
                    float p = ep[lin];
                    size_t oi = (size_t)(rbase + r) * N + col;
                    if (MODE == MODE_FWD) {
                        p += bias[col];
                        out1[oi] = sigmoidf_(p);
                        out2[oi] = wmma::__float_to_tf32(softplusf(p));
                    } else if (MODE == MODE_L4) {
                        p += bias[col];
                        out1[oi] = wmma::__float_to_tf32(vecn[col] * sigmoidf_(p));
                    } else if (MODE == MODE_BWD) {
                        out1[oi] = wmma::__float_to_tf32(sgate[oi] * p);
                    } else { // MODE_FIN
                        out1[oi] = p + vecn[col];
                    }
                }
            }
            __syncwarp();
        }
    }
}

// ---------------- host launcher ----------------
extern "C" void kernel_launch(void* const* d_in, const int* in_sizes, int n_in,
                              void* d_out, int out_size)
{
    const float* state = (const float*)d_in[0];
    const float* Wz0   = (const float*)d_in[1];
    const float* bz0   = (const float*)d_in[2];
    const float* Wz1   = (const float*)d_in[3];
    const float* Wz2   = (const float*)d_in[4];
    const float* Wz3   = (const float*)d_in[5];
    const float* WzL   = (const float*)d_in[6];
    const float* Wx0   = (const float*)d_in[7];
    const float* bx0   = (const float*)d_in[8];
    const float* Wx1   = (const float*)d_in[9];
    const float* bx1   = (const float*)d_in[10];
    const float* Wx2   = (const float*)d_in[11];
    const float* bx2   = (const float*)d_in[12];
    const float* WxL   = (const float*)d_in[13];
    float* out = (float*)d_out;

    cudaFuncSetAttribute(gemm_fused<true,  MODE_FWD>, cudaFuncAttributeMaxDynamicSharedMemorySize, SMEM_BYTES);
    cudaFuncSetAttribute(gemm_fused<true,  MODE_L4>,  cudaFuncAttributeMaxDynamicSharedMemorySize, SMEM_BYTES);
    cudaFuncSetAttribute(gemm_fused<false, MODE_BWD>, cudaFuncAttributeMaxDynamicSharedMemorySize, SMEM_BYTES);
    cudaFuncSetAttribute(gemm_fused<false, MODE_FIN>, cudaFuncAttributeMaxDynamicSharedMemorySize, SMEM_BYTES);

    void* p;
    float *xm1, *s1, *s2, *s3, *a1, *a2, *a3, *d1, *d2, *d3, *d4;
    float *wz0, *wz1, *wz2, *wz3, *wx0, *wx1, *wx2;
    cudaGetSymbolAddress(&p, g_xm1); xm1 = (float*)p;
    cudaGetSymbolAddress(&p, g_s1);  s1  = (float*)p;
    cudaGetSymbolAddress(&p, g_s2);  s2  = (float*)p;
    cudaGetSymbolAddress(&p, g_s3);  s3  = (float*)p;
    cudaGetSymbolAddress(&p, g_a1);  a1  = (float*)p;
    cudaGetSymbolAddress(&p, g_a2);  a2  = (float*)p;
    cudaGetSymbolAddress(&p, g_a3);  a3  = (float*)p;
    cudaGetSymbolAddress(&p, g_d1);  d1  = (float*)p;
    cudaGetSymbolAddress(&p, g_d2);  d2  = (float*)p;
    cudaGetSymbolAddress(&p, g_d3);  d3  = (float*)p;
    cudaGetSymbolAddress(&p, g_d4);  d4  = (float*)p;
    cudaGetSymbolAddress(&p, g_wz0); wz0 = (float*)p;
    cudaGetSymbolAddress(&p, g_wz1); wz1 = (float*)p;
    cudaGetSymbolAddress(&p, g_wz2); wz2 = (float*)p;
    cudaGetSymbolAddress(&p, g_wz3); wz3 = (float*)p;
    cudaGetSymbolAddress(&p, g_wx0); wx0 = (float*)p;
    cudaGetSymbolAddress(&p, g_wx1); wx1 = (float*)p;
    cudaGetSymbolAddress(&p, g_wx2); wx2 = (float*)p;

    const int nX = BATCH * DIN;
    sub1_kernel<<<(nX + 255) / 256, 256>>>(state, xm1, nX);

    // Pre-round all GEMM weights to tf32 (tiny)
    round_copy_kernel<<<(HID*DIN + 255)/256, 256>>>(Wz0, wz0, HID*DIN);
    round_copy_kernel<<<(HID*HID + 255)/256, 256>>>(Wz1, wz1, HID*HID);
    round_copy_kernel<<<(HID*HID + 255)/256, 256>>>(Wz2, wz2, HID*HID);
    round_copy_kernel<<<(HID*HID + 255)/256, 256>>>(Wz3, wz3, HID*HID);
    round_copy_kernel<<<(HID*DIN + 255)/256, 256>>>(Wx0, wx0, HID*DIN);
    round_copy_kernel<<<(HID*DIN + 255)/256, 256>>>(Wx1, wx1, HID*DIN);
    round_copy_kernel<<<(HID*DIN + 255)/256, 256>>>(Wx2, wx2, HID*DIN);

    dim3 blk(NTHREADS);
    dim3 gH(HID / BN, BATCH / BM);   // (4, 512)
    dim3 gF(1, BATCH / BM);          // (1, 512)

    // Forward
    gemm_fused<true, MODE_FWD><<<gH, blk, SMEM_BYTES>>>(xm1, wz0, DIN,
                                  nullptr, nullptr, 0,
                                  nullptr, nullptr, 0,
                                  nullptr, nullptr, 0,
                                  HID, bz0, nullptr, nullptr, s1, a1);
    gemm_fused<true, MODE_FWD><<<gH, blk, SMEM_BYTES>>>(a1, wz1, HID,
                                  xm1, wx0, DIN,
                                  nullptr, nullptr, 0,
                                  nullptr, nullptr, 0,
                                  HID, bx0, nullptr, nullptr, s2, a2);
    gemm_fused<true, MODE_FWD><<<gH, blk, SMEM_BYTES>>>(a2, wz2, HID,
                                  xm1, wx1, DIN,
                                  nullptr, nullptr, 0,
                                  nullptr, nullptr, 0,
                                  HID, bx1, nullptr, nullptr, s3, a3);
    gemm_fused<true, MODE_L4><<<gH, blk, SMEM_BYTES>>>(a3, wz3, HID,
                                  xm1, wx2, DIN,
                                  nullptr, nullptr, 0,
                                  nullptr, nullptr, 0,
                                  HID, bx2, WzL, nullptr, d4, nullptr);

    // Backward (u = d_next @ Wz_k row-major; d = s ⊙ u)
    gemm_fused<false, MODE_BWD><<<gH, blk, SMEM_BYTES>>>(d4, wz3, HID,
                                   nullptr, nullptr, 0,
                                   nullptr, nullptr, 0,
                                   nullptr, nullptr, 0,
                                   HID, nullptr, nullptr, s3, d3, nullptr);
    gemm_fused<false, MODE_BWD><<<gH, blk, SMEM_BYTES>>>(d3, wz2, HID,
                                   nullptr, nullptr, 0,
                                   nullptr, nullptr, 0,
                                   nullptr, nullptr, 0,
                                   HID, nullptr, nullptr, s2, d2, nullptr);
    gemm_fused<false, MODE_BWD><<<gH, blk, SMEM_BYTES>>>(d2, wz1, HID,
                                   nullptr, nullptr, 0,
                                   nullptr, nullptr, 0,
                                   nullptr, nullptr, 0,
                                   HID, nullptr, nullptr, s1, d1, nullptr);

    // Final: action = WxL + d1@Wz0 + d2@Wx0 + d3@Wx1 + d4@Wx2
    gemm_fused<false, MODE_FIN><<<gF, blk, SMEM_BYTES>>>(d1, wz0, HID,
                                   d2, wx0, HID,
                                   d3, wx1, HID,
                                   d4, wx2, HID,
                                   DIN, nullptr, WxL, nullptr, out, nullptr);
}

// round 10
// speedup vs baseline: 5.6547x; 2.8507x over previous
#include <cuda_runtime.h>
#include <cuda_fp16.h>
#include <mma.h>
#include <math.h>
#include <cstdint>

using namespace nvcuda;

// Problem shapes
#define BATCH 65536
#define DIN   64
#define HID   512

// GEMM tile config (fp16 operands, fp32 accum)
#define BM 128
#define BN 128
#define BKC 64
#define LDA_H 72     // 64 + 8 pad halfs (144B rows, 16B-aligned)
#define LDB_H 144    // 128 + 16 pad halfs (288B rows, 16B-aligned)
#define NTHREADS 256
#define STAGES 3

#define A_STAGE_HALFS (BM * LDA_H)     // 9216
#define W_STAGE_HALFS 9216             // max(128*72, 64*144) = 9216
#define STAGE_HALFS  (A_STAGE_HALFS + W_STAGE_HALFS)   // 18432
#define SMEM_BYTES   (STAGES * STAGE_HALFS * 2)        // 110592

// ---------------- scratch (device globals; no allocation) ----------------
__device__ __align__(256) __half g_xm1[BATCH * DIN];
__device__ __align__(256) __half g_s1[BATCH * HID];
__device__ __align__(256) __half g_s2[BATCH * HID];
__device__ __align__(256) __half g_s3[BATCH * HID];
__device__ __align__(256) __half g_a1[BATCH * HID];
__device__ __align__(256) __half g_a2[BATCH * HID];
__device__ __align__(256) __half g_a3[BATCH * HID];
__device__ __align__(256) __half g_d1[BATCH * HID];
__device__ __align__(256) __half g_d2[BATCH * HID];
__device__ __align__(256) __half g_d3[BATCH * HID];
__device__ __align__(256) __half g_d4[BATCH * HID];
// fp16 weight copies (original layouts)
__device__ __align__(256) __half g_wz0[HID * DIN];
__device__ __align__(256) __half g_wz1[HID * HID];
__device__ __align__(256) __half g_wz2[HID * HID];
__device__ __align__(256) __half g_wz3[HID * HID];
__device__ __align__(256) __half g_wx0[HID * DIN];
__device__ __align__(256) __half g_wx1[HID * DIN];
__device__ __align__(256) __half g_wx2[HID * DIN];

// ---------------- prep kernels ----------------
__global__ void sub1_half_kernel(const float* __restrict__ in, __half* __restrict__ out, int n) {
    int i = blockIdx.x * blockDim.x + threadIdx.x;
    if (i < n) out[i] = __float2half_rn(in[i] - 1.0f);
}
__global__ void copy_half_kernel(const float* __restrict__ in, __half* __restrict__ out, int n) {
    int i = blockIdx.x * blockDim.x + threadIdx.x;
    if (i < n) out[i] = __float2half_rn(in[i]);
}

// ---------------- helpers ----------------
__device__ __forceinline__ float softplusf(float p) { return (p > 20.0f) ? p : log1pf(expf(p)); }
__device__ __forceinline__ float sigmoidf_(float p) { return 1.0f / (1.0f + expf(-p)); }

__device__ __forceinline__ void cp_async16(__half* smem_dst, const __half* gmem_src, bool pred) {
    unsigned int s = (unsigned int)__cvta_generic_to_shared(smem_dst);
    int bytes = pred ? 16 : 0;
    asm volatile("cp.async.cg.shared.global [%0], [%1], 16, %2;\n"
                 :: "r"(s), "l"(gmem_src), "r"(bytes));
}
__device__ __forceinline__ void cp_commit() { asm volatile("cp.async.commit_group;\n" ::: "memory"); }
__device__ __forceinline__ void cp_wait0() { asm volatile("cp.async.wait_group 0;\n" ::: "memory"); }
__device__ __forceinline__ void cp_wait1() { asm volatile("cp.async.wait_group 1;\n" ::: "memory"); }

// Epilogue modes
#define MODE_FWD 0   // out1h = sigmoid(p+b), out2h = softplus(p+b)
#define MODE_L4  1   // out1h = vecn[col] * sigmoid(p+b)
#define MODE_BWD 2   // out1h = sgate[oi] * p
#define MODE_FIN 3   // out1f = p + vecn[col]

// Map flattened 64-wide K-chunk index -> segment
__device__ __forceinline__ void get_iter(
    int it,
    const __half* A0, const __half* W0, int K0,
    const __half* A1, const __half* W1, int K1,
    const __half* A2, const __half* W2, int K2,
    const __half* A3, const __half* W3, int K3,
    const __half*& A, const __half*& W, int& K, int& k0)
{
    int n0 = K0 >> 6;
    if (it < n0) { A = A0; W = W0; K = K0; k0 = it << 6; return; }
    it -= n0;
    int n1 = K1 >> 6;
    if (it < n1) { A = A1; W = W1; K = K1; k0 = it << 6; return; }
    it -= n1;
    int n2 = K2 >> 6;
    if (it < n2) { A = A2; W = W2; K = K2; k0 = it << 6; return; }
    it -= n2;
    A = A3; W = W3; K = K3; k0 = it << 6;
}

// Stage one K-chunk: A tile [128 x 64] halfs; W tile.
// BT=true : W [N,K] row-major -> sW[n*LDA_H + k]  (forward: B = W^T)
// BT=false: W [K,N] row-major -> sW[k*LDB_H + n]  (backward/final: B = W)
template<bool BT>
__device__ __forceinline__ void stage_tiles(
    __half* sA, __half* sW,
    const __half* __restrict__ A, const __half* __restrict__ W,
    int K, int k0, int m0, int n0, int N, int tid)
{
    // A: 128 rows x 8 chunks (8 halfs each) = 1024 chunks, 4/thread
    #pragma unroll
    for (int t = 0; t < 4; t++) {
        int slot = tid + t * NTHREADS;
        int row = slot >> 3, kq = slot & 7;
        cp_async16(&sA[row * LDA_H + (kq << 3)],
                   A + (size_t)(m0 + row) * K + k0 + (kq << 3), true);
    }
    if (BT) {
        #pragma unroll
        for (int t = 0; t < 4; t++) {
            int slot = tid + t * NTHREADS;
            int n = slot >> 3, kq = slot & 7;
            cp_async16(&sW[n * LDA_H + (kq << 3)],
                       W + (size_t)(n0 + n) * K + k0 + (kq << 3), true);
        }
    } else {
        // 64 rows x 16 chunks = 1024 chunks, 4/thread
        #pragma unroll
        for (int t = 0; t < 4; t++) {
            int slot = tid + t * NTHREADS;
            int krow = slot >> 4, nq = slot & 15;
            int col = n0 + (nq << 3);
            cp_async16(&sW[krow * LDB_H + (nq << 3)],
                       W + (size_t)(k0 + krow) * N + col, col < N);
        }
    }
}

// fp16 fused GEMM, 3-stage cp.async ring, one __syncthreads per iteration.
template<bool BT, int MODE>
__global__ void __launch_bounds__(NTHREADS, 2)
gemm_h(const __half* __restrict__ A0, const __half* __restrict__ W0, int K0,
       const __half* __restrict__ A1, const __half* __restrict__ W1, int K1,
       const __half* __restrict__ A2, const __half* __restrict__ W2, int K2,
       const __half* __restrict__ A3, const __half* __restrict__ W3, int K3,
       int N,
       const float* __restrict__ bias,
       const float* __restrict__ vecn,
       const __half* __restrict__ sgate,
       __half* __restrict__ out1h,
       __half* __restrict__ out2h,
       float* __restrict__ out1f)
{
    extern __shared__ __half smem_h[];

    const int tid    = threadIdx.x;
    const int warpId = tid >> 5;
    const int lane   = tid & 31;
    const int wm     = warpId >> 2;   // 0..1
    const int wn     = warpId & 3;    // 0..3
    const int m0     = blockIdx.y * BM;
    const int n0     = blockIdx.x * BN;

    wmma::fragment<wmma::accumulator, 16, 16, 16, float> acc[4][2];
    #pragma unroll
    for (int i = 0; i < 4; i++)
        #pragma unroll
        for (int j = 0; j < 2; j++)
            wmma::fill_fragment(acc[i][j], 0.0f);

    const int niter = (K0 >> 6) + (K1 >> 6) + (K2 >> 6) + (K3 >> 6);

    // prologue: stage chunk 0 and 1
    #pragma unroll
    for (int j = 0; j < 2; j++) {
        if (j < niter) {
            const __half *A, *W; int K, k0;
            get_iter(j, A0,W0,K0, A1,W1,K1, A2,W2,K2, A3,W3,K3, A, W, K, k0);
            stage_tiles<BT>(smem_h + j * STAGE_HALFS,
                            smem_h + j * STAGE_HALFS + A_STAGE_HALFS,
                            A, W, K, k0, m0, n0, N, tid);
            cp_commit();
        }
    }

    for (int it = 0; it < niter; ++it) {
        if (it + 1 < niter) cp_wait1(); else cp_wait0();
        __syncthreads();

        // stage it+2 (that buffer was last computed at it-1, safe after sync)
        const int nxt = it + 2;
        if (nxt < niter) {
            const __half *A, *W; int K, k0;
            get_iter(nxt, A0,W0,K0, A1,W1,K1, A2,W2,K2, A3,W3,K3, A, W, K, k0);
            __half* nb = smem_h + (nxt % STAGES) * STAGE_HALFS;
            stage_tiles<BT>(nb, nb + A_STAGE_HALFS, A, W, K, k0, m0, n0, N, tid);
            cp_commit();
        }

        __half* sA = smem_h + (it % STAGES) * STAGE_HALFS;
        __half* sW = sA + A_STAGE_HALFS;

        #pragma unroll
        for (int kk = 0; kk < BKC; kk += 16) {
            wmma::fragment<wmma::matrix_a, 16, 16, 16, __half, wmma::row_major> af[4];
            #pragma unroll
            for (int i = 0; i < 4; i++)
                wmma::load_matrix_sync(af[i], &sA[(wm * 64 + i * 16) * LDA_H + kk], LDA_H);
            if (BT) {
                wmma::fragment<wmma::matrix_b, 16, 16, 16, __half, wmma::col_major> bf[2];
                #pragma unroll
                for (int j = 0; j < 2; j++)
                    wmma::load_matrix_sync(bf[j], &sW[(wn * 32 + j * 16) * LDA_H + kk], LDA_H);
                #pragma unroll
                for (int i = 0; i < 4; i++)
                    #pragma unroll
                    for (int j = 0; j < 2; j++)
                        wmma::mma_sync(acc[i][j], af[i], bf[j], acc[i][j]);
            } else {
                wmma::fragment<wmma::matrix_b, 16, 16, 16, __half, wmma::row_major> bf[2];
                #pragma unroll
                for (int j = 0; j < 2; j++)
                    wmma::load_matrix_sync(bf[j], &sW[kk * LDB_H + wn * 32 + j * 16], LDB_H);
                #pragma unroll
                for (int i = 0; i < 4; i++)
                    #pragma unroll
                    for (int j = 0; j < 2; j++)
                        wmma::mma_sync(acc[i][j], af[i], bf[j], acc[i][j]);
            }
        }
    }

    // ---- epilogue ----
    __syncthreads();
    float* ep = reinterpret_cast<float*>(smem_h) + warpId * 288;

    #pragma unroll
    for (int i = 0; i < 4; i++) {
        #pragma unroll
        for (int j = 0; j < 2; j++) {
            const int rbase = m0 + wm * 64 + i * 16;
            const int cbase = n0 + wn * 32 + j * 16;
            wmma::store_matrix_sync(ep, acc[i][j], 16, wmma::mem_row_major);
            __syncwarp();
            #pragma unroll
            for (int e = 0; e < 8; e++) {
                int lin = e * 32 + lane;
                int r = lin >> 4;
                int c = lin & 15;
                int col = cbase + c;
                if (col < N) {
                    float p = ep[lin];
                    size_t oi = (size_t)(rbase + r) * N + col;
                    if (MODE == MODE_FWD) {
                        p += bias[col];
                        out1h[oi] = __float2half_rn(sigmoidf_(p));
                        out2h[oi] = __float2half_rn(softplusf(p));
                    } else if (MODE == MODE_L4) {
                        p += bias[col];
                        out1h[oi] = __float2half_rn(vecn[col] * sigmoidf_(p));
                    } else if (MODE == MODE_BWD) {
                        out1h[oi] = __float2half_rn(__half2float(sgate[oi]) * p);
                    } else { // MODE_FIN
                        out1f[oi] = p + vecn[col];
                    }
                }
            }
            __syncwarp();
        }
    }
}

// ---------------- host launcher ----------------
extern "C" void kernel_launch(void* const* d_in, const int* in_sizes, int n_in,
                              void* d_out, int out_size)
{
    const float* state = (const float*)d_in[0];
    const float* Wz0   = (const float*)d_in[1];
    const float* bz0   = (const float*)d_in[2];
    const float* Wz1   = (const float*)d_in[3];
    const float* Wz2   = (const float*)d_in[4];
    const float* Wz3   = (const float*)d_in[5];
    const float* WzL   = (const float*)d_in[6];
    const float* Wx0   = (const float*)d_in[7];
    const float* bx0   = (const float*)d_in[8];
    const float* Wx1   = (const float*)d_in[9];
    const float* bx1   = (const float*)d_in[10];
    const float* Wx2   = (const float*)d_in[11];
    const float* bx2   = (const float*)d_in[12];
    const float* WxL   = (const float*)d_in[13];
    float* out = (float*)d_out;

    cudaFuncSetAttribute(gemm_h<true,  MODE_FWD>, cudaFuncAttributeMaxDynamicSharedMemorySize, SMEM_BYTES);
    cudaFuncSetAttribute(gemm_h<true,  MODE_L4>,  cudaFuncAttributeMaxDynamicSharedMemorySize, SMEM_BYTES);
    cudaFuncSetAttribute(gemm_h<false, MODE_BWD>, cudaFuncAttributeMaxDynamicSharedMemorySize, SMEM_BYTES);
    cudaFuncSetAttribute(gemm_h<false, MODE_FIN>, cudaFuncAttributeMaxDynamicSharedMemorySize, SMEM_BYTES);

    void* p;
    __half *xm1, *s1, *s2, *s3, *a1, *a2, *a3, *d1, *d2, *d3, *d4;
    __half *wz0, *wz1, *wz2, *wz3, *wx0, *wx1, *wx2;
    cudaGetSymbolAddress(&p, g_xm1);  xm1  = (__half*)p;
    cudaGetSymbolAddress(&p, g_s1);   s1   = (__half*)p;
    cudaGetSymbolAddress(&p, g_s2);   s2   = (__half*)p;
    cudaGetSymbolAddress(&p, g_s3);   s3   = (__half*)p;
    cudaGetSymbolAddress(&p, g_a1);   a1   = (__half*)p;
    cudaGetSymbolAddress(&p, g_a2);   a2   = (__half*)p;
    cudaGetSymbolAddress(&p, g_a3);   a3   = (__half*)p;
    cudaGetSymbolAddress(&p, g_d1);   d1   = (__half*)p;
    cudaGetSymbolAddress(&p, g_d2);   d2   = (__half*)p;
    cudaGetSymbolAddress(&p, g_d3);   d3   = (__half*)p;
    cudaGetSymbolAddress(&p, g_d4);   d4   = (__half*)p;
    cudaGetSymbolAddress(&p, g_wz0);  wz0  = (__half*)p;
    cudaGetSymbolAddress(&p, g_wz1);  wz1  = (__half*)p;
    cudaGetSymbolAddress(&p, g_wz2);  wz2  = (__half*)p;
    cudaGetSymbolAddress(&p, g_wz3);  wz3  = (__half*)p;
    cudaGetSymbolAddress(&p, g_wx0);  wx0  = (__half*)p;
    cudaGetSymbolAddress(&p, g_wx1);  wx1  = (__half*)p;
    cudaGetSymbolAddress(&p, g_wx2);  wx2  = (__half*)p;

    const int nX = BATCH * DIN;
    sub1_half_kernel<<<(nX + 255) / 256, 256>>>(state, xm1, nX);

    copy_half_kernel<<<(HID*DIN + 255)/256, 256>>>(Wz0, wz0, HID*DIN);
    copy_half_kernel<<<(HID*HID + 255)/256, 256>>>(Wz1, wz1, HID*HID);
    copy_half_kernel<<<(HID*HID + 255)/256, 256>>>(Wz2, wz2, HID*HID);
    copy_half_kernel<<<(HID*HID + 255)/256, 256>>>(Wz3, wz3, HID*HID);
    copy_half_kernel<<<(HID*DIN + 255)/256, 256>>>(Wx0, wx0, HID*DIN);
    copy_half_kernel<<<(HID*DIN + 255)/256, 256>>>(Wx1, wx1, HID*DIN);
    copy_half_kernel<<<(HID*DIN + 255)/256, 256>>>(Wx2, wx2, HID*DIN);

    dim3 blk(NTHREADS);
    dim3 gH(HID / BN, BATCH / BM);   // (4, 512)
    dim3 gF(1, BATCH / BM);          // (1, 512)

    // Forward (BT=true: B = W^T, W is [N,K] row-major)
    gemm_h<true, MODE_FWD><<<gH, blk, SMEM_BYTES>>>(xm1, wz0, DIN,
        nullptr, nullptr, 0, nullptr, nullptr, 0, nullptr, nullptr, 0,
        HID, bz0, nullptr, nullptr, s1, a1, nullptr);
    gemm_h<true, MODE_FWD><<<gH, blk, SMEM_BYTES>>>(a1, wz1, HID,
        xm1, wx0, DIN, nullptr, nullptr, 0, nullptr, nullptr, 0,
        HID, bx0, nullptr, nullptr, s2, a2, nullptr);
    gemm_h<true, MODE_FWD><<<gH, blk, SMEM_BYTES>>>(a2, wz2, HID,
        xm1, wx1, DIN, nullptr, nullptr, 0, nullptr, nullptr, 0,
        HID, bx1, nullptr, nullptr, s3, a3, nullptr);
    gemm_h<true, MODE_L4><<<gH, blk, SMEM_BYTES>>>(a3, wz3, HID,
        xm1, wx2, DIN, nullptr, nullptr, 0, nullptr, nullptr, 0,
        HID, bx2, WzL, nullptr, d4, nullptr, nullptr);

    // Backward: d_k = s_k * (d_{k+1} @ Wz_{k+1}); Wz is [K,N] row-major -> BT=false
    gemm_h<false, MODE_BWD><<<gH, blk, SMEM_BYTES>>>(d4, wz3, HID,
        nullptr, nullptr, 0, nullptr, nullptr, 0, nullptr, nullptr, 0,
        HID, nullptr, nullptr, s3, d3, nullptr, nullptr);
    gemm_h<false, MODE_BWD><<<gH, blk, SMEM_BYTES>>>(d3, wz2, HID,
        nullptr, nullptr, 0, nullptr, nullptr, 0, nullptr, nullptr, 0,
        HID, nullptr, nullptr, s2, d2, nullptr, nullptr);
    gemm_h<false, MODE_BWD><<<gH, blk, SMEM_BYTES>>>(d2, wz1, HID,
        nullptr, nullptr, 0, nullptr, nullptr, 0, nullptr, nullptr, 0,
        HID, nullptr, nullptr, s1, d1, nullptr, nullptr);

    // Final: action = WxL + d1@Wz0 + d2@Wx0 + d3@Wx1 + d4@Wx2
    // Wz0/Wx* are [HID, DIN] row-major = [K,N] -> BT=false
    gemm_h<false, MODE_FIN><<<gF, blk, SMEM_BYTES>>>(d1, wz0, HID,
        d2, wx0, HID, d3, wx1, HID, d4, wx2, HID,
        DIN, nullptr, WxL, nullptr, nullptr, nullptr, out);
}